// round 2
// baseline (speedup 1.0000x reference)
#include <cuda_runtime.h>
#include <cuda_bf16.h>

#define NN 50000
#define EE 800000
#define DIM 128   // IN == H*C == 128

// ---------------- scratch (static device allocations are allowed) -------------
__device__ float g_q[(size_t)NN * DIM];
__device__ float g_k[(size_t)NN * DIM];
__device__ float g_v[(size_t)NN * DIM];
__device__ int   g_deg[NN];
__device__ int   g_cursor[NN];
__device__ int   g_off[NN + 1];
__device__ int   g_csr[EE];
__device__ int   g_is32;   // 1 if edge_index buffer is int32, 0 if int64

// ---------------- dtype detection --------------------------------------------
// Reference declares int64, but JAX default config (x64 disabled) silently
// yields int32. Detect: interpret as int64; with int32 data the packed pairs
// (lo + hi<<32) blow past NN almost surely within 1024 samples.
__global__ void detect_kernel(const void* __restrict__ ei) {
    const long long* p64 = (const long long*)ei;
    int is32 = 0;
    for (int i = 0; i < 1024; i++) {
        long long v = p64[i];
        if (v < 0 || v >= (long long)NN) { is32 = 1; break; }
    }
    g_is32 = is32;
}

__device__ __forceinline__ int edge_src(const void* ei, int e) {
    if (g_is32) return ((const int*)ei)[e];
    return (int)((const long long*)ei)[e];
}
__device__ __forceinline__ int edge_dst(const void* ei, int e) {
    if (g_is32) return ((const int*)ei)[EE + e];
    return (int)((const long long*)ei)[EE + e];
}

// ---------------- CSR build ---------------------------------------------------
__global__ void init_kernel() {
    int i = blockIdx.x * blockDim.x + threadIdx.x;
    if (i < NN) { g_deg[i] = 0; g_cursor[i] = 0; }
}

__global__ void hist_kernel(const void* __restrict__ ei) {
    int e = blockIdx.x * blockDim.x + threadIdx.x;
    if (e < EE) {
        int dst = edge_dst(ei, e);
        if ((unsigned)dst < (unsigned)NN)
            atomicAdd(&g_deg[dst], 1);
    }
}

// single-block exclusive scan over g_deg -> g_off
__global__ void scan_kernel() {
    __shared__ int wsum[32];
    __shared__ int carry_s;
    int tid = threadIdx.x, lane = tid & 31, wid = tid >> 5;
    if (tid == 0) carry_s = 0;
    __syncthreads();
    for (int base = 0; base < NN; base += 1024) {
        int i = base + tid;
        int v = (i < NN) ? g_deg[i] : 0;
        int s = v;
        #pragma unroll
        for (int d = 1; d < 32; d <<= 1) {
            int t = __shfl_up_sync(0xffffffffu, s, d);
            if (lane >= d) s += t;
        }
        if (lane == 31) wsum[wid] = s;
        __syncthreads();
        if (wid == 0) {
            int ws = wsum[lane];
            #pragma unroll
            for (int d = 1; d < 32; d <<= 1) {
                int t = __shfl_up_sync(0xffffffffu, ws, d);
                if (lane >= d) ws += t;
            }
            wsum[lane] = ws;
        }
        __syncthreads();
        int carry = carry_s;
        int excl = carry + (s - v) + (wid ? wsum[wid - 1] : 0);
        if (i < NN) g_off[i] = excl;
        __syncthreads();
        if (tid == 0) carry_s += wsum[31];
        __syncthreads();
    }
    if (tid == 0) g_off[NN] = carry_s;
}

__global__ void fill_kernel(const void* __restrict__ ei) {
    int e = blockIdx.x * blockDim.x + threadIdx.x;
    if (e < EE) {
        int src = edge_src(ei, e);
        int dst = edge_dst(ei, e);
        if ((unsigned)dst < (unsigned)NN && (unsigned)src < (unsigned)NN) {
            int pos = g_off[dst] + atomicAdd(&g_cursor[dst], 1);
            if ((unsigned)pos < (unsigned)EE)
                g_csr[pos] = src;
        }
    }
}

// ---------------- GEMM: y = x @ W + b  (128x128 tile, 8x8 micro) -------------
// grid.y selects (Wq->g_q, Wk->g_k, Wv->g_v, Wskip->d_out)
__global__ __launch_bounds__(256) void gemm_kernel(
    const float* __restrict__ x,
    const float* __restrict__ Wq, const float* __restrict__ bq,
    const float* __restrict__ Wk, const float* __restrict__ bk,
    const float* __restrict__ Wv, const float* __restrict__ bv,
    const float* __restrict__ Ws, const float* __restrict__ bs,
    float* __restrict__ dout)
{
    const float* W; const float* bias; float* out;
    switch (blockIdx.y) {
        case 0:  W = Wq; bias = bq; out = g_q;  break;
        case 1:  W = Wk; bias = bk; out = g_k;  break;
        case 2:  W = Wv; bias = bv; out = g_v;  break;
        default: W = Ws; bias = bs; out = dout; break;
    }

    __shared__ float xs[16][132];  // transposed x tile: xs[k][m]
    __shared__ float ws[16][132];  // ws[k][n]

    const int tid = threadIdx.x;           // 256 threads
    const int m_base = blockIdx.x * 128;
    const int tx = tid & 15;               // col group 0..15
    const int ty = tid >> 4;               // row group 0..15
    const int c0 = tx * 8;
    const int r0 = ty * 8;

    float acc[8][8];
    #pragma unroll
    for (int r = 0; r < 8; r++)
        #pragma unroll
        for (int c = 0; c < 8; c++) acc[r][c] = 0.f;

    for (int kc = 0; kc < 128; kc += 16) {
        // load x tile (128 rows x 16 k), store transposed
        #pragma unroll
        for (int i = 0; i < 2; i++) {
            int id = tid + i * 256;        // 0..511
            int m  = id >> 2;              // 0..127
            int k4 = (id & 3) * 4;         // 0,4,8,12
            int row = m_base + m;
            float4 xv = make_float4(0.f, 0.f, 0.f, 0.f);
            if (row < NN)
                xv = *(const float4*)(x + (size_t)row * DIM + kc + k4);
            xs[k4 + 0][m] = xv.x; xs[k4 + 1][m] = xv.y;
            xs[k4 + 2][m] = xv.z; xs[k4 + 3][m] = xv.w;
        }
        // load W tile (16 k rows x 128 cols), straight copy
        #pragma unroll
        for (int i = 0; i < 2; i++) {
            int id = tid + i * 256;
            int kk = id >> 5;              // 0..15
            int n4 = (id & 31) * 4;        // 0..124
            float4 wv = *(const float4*)(W + (size_t)(kc + kk) * DIM + n4);
            *(float4*)&ws[kk][n4] = wv;
        }
        __syncthreads();

        #pragma unroll
        for (int kk = 0; kk < 16; kk++) {
            float a[8], bb[8];
            #pragma unroll
            for (int i = 0; i < 8; i += 4) {
                float4 t = *(float4*)&xs[kk][r0 + i];
                a[i] = t.x; a[i + 1] = t.y; a[i + 2] = t.z; a[i + 3] = t.w;
            }
            #pragma unroll
            for (int i = 0; i < 8; i += 4) {
                float4 t = *(float4*)&ws[kk][c0 + i];
                bb[i] = t.x; bb[i + 1] = t.y; bb[i + 2] = t.z; bb[i + 3] = t.w;
            }
            #pragma unroll
            for (int r = 0; r < 8; r++)
                #pragma unroll
                for (int c = 0; c < 8; c++)
                    acc[r][c] += a[r] * bb[c];
        }
        __syncthreads();
    }

    // epilogue: add bias, store float4
    float bv4[8];
    #pragma unroll
    for (int c = 0; c < 8; c++) bv4[c] = bias[c0 + c];
    #pragma unroll
    for (int r = 0; r < 8; r++) {
        int row = m_base + r0 + r;
        if (row < NN) {
            #pragma unroll
            for (int c = 0; c < 8; c += 4) {
                float4 o;
                o.x = acc[r][c + 0] + bv4[c + 0];
                o.y = acc[r][c + 1] + bv4[c + 1];
                o.z = acc[r][c + 2] + bv4[c + 2];
                o.w = acc[r][c + 3] + bv4[c + 3];
                *(float4*)(out + (size_t)row * DIM + c0 + c) = o;
            }
        }
    }
}

// ---------------- fused attention: one warp per dst node ---------------------
// softmax without max-subtraction (alpha sigma ~0.33, exp is safe):
//   out[n] += (sum_e exp(a_e) * v[src_e]) / (sum_e exp(a_e))
__global__ void attn_kernel(float* __restrict__ dout) {
    int warp = (blockIdx.x * blockDim.x + threadIdx.x) >> 5;
    if (warp >= NN) return;
    int lane = threadIdx.x & 31;

    const float4 qv = *(const float4*)(g_q + (size_t)warp * DIM + lane * 4);
    float4 acc = make_float4(0.f, 0.f, 0.f, 0.f);
    float denom = 0.f;

    const int e0 = g_off[warp];
    const int e1 = g_off[warp + 1];
    const float inv_sqrt_c = 0.17677669529663688f;  // 1/sqrt(32)

    for (int j = e0; j < e1; ++j) {
        int s = g_csr[j];
        const float4 kv = *(const float4*)(g_k + (size_t)s * DIM + lane * 4);
        float p = qv.x * kv.x + qv.y * kv.y + qv.z * kv.z + qv.w * kv.w;
        // reduce over the 8 lanes of this head (lanes grouped 8-per-head)
        p += __shfl_xor_sync(0xffffffffu, p, 1);
        p += __shfl_xor_sync(0xffffffffu, p, 2);
        p += __shfl_xor_sync(0xffffffffu, p, 4);
        float ex = __expf(p * inv_sqrt_c);
        const float4 vv = *(const float4*)(g_v + (size_t)s * DIM + lane * 4);
        acc.x += ex * vv.x; acc.y += ex * vv.y;
        acc.z += ex * vv.z; acc.w += ex * vv.w;
        denom += ex;
    }

    float inv = (denom > 0.f) ? (1.f / denom) : 0.f;
    float4* op = (float4*)(dout + (size_t)warp * DIM + lane * 4);
    float4 cur = *op;   // holds skip projection from GEMM
    cur.x += acc.x * inv; cur.y += acc.y * inv;
    cur.z += acc.z * inv; cur.w += acc.w * inv;
    *op = cur;
}

// ---------------- launch ------------------------------------------------------
extern "C" void kernel_launch(void* const* d_in, const int* in_sizes, int n_in,
                              void* d_out, int out_size) {
    const float* x   = (const float*)d_in[0];
    const void*  ei  = d_in[1];
    const float* Wq  = (const float*)d_in[2];
    const float* bq  = (const float*)d_in[3];
    const float* Wk  = (const float*)d_in[4];
    const float* bk  = (const float*)d_in[5];
    const float* Wv  = (const float*)d_in[6];
    const float* bv  = (const float*)d_in[7];
    const float* Ws  = (const float*)d_in[8];
    const float* bs  = (const float*)d_in[9];
    float* dout = (float*)d_out;

    detect_kernel<<<1, 1>>>(ei);
    init_kernel<<<(NN + 255) / 256, 256>>>();
    hist_kernel<<<(EE + 255) / 256, 256>>>(ei);
    scan_kernel<<<1, 1024>>>();
    fill_kernel<<<(EE + 255) / 256, 256>>>(ei);

    dim3 ggrid((NN + 127) / 128, 4);
    gemm_kernel<<<ggrid, 256>>>(x, Wq, bq, Wk, bk, Wv, bv, Ws, bs, dout);

    attn_kernel<<<(NN * 32 + 255) / 256, 256>>>(dout);
}

// round 3
// speedup vs baseline: 1.2568x; 1.2568x over previous
#include <cuda_runtime.h>
#include <cuda_bf16.h>
#include <cstdint>

#define NN 50000
#define EE 800000
#define DIM 128   // IN == H*C == 128
#define NB 49     // ceil(NN/1024)

// ---------------- scratch -----------------------------------------------------
__device__ float g_q[(size_t)NN * DIM];
__device__ float g_k[(size_t)NN * DIM];
__device__ float g_v[(size_t)NN * DIM];
__device__ int   g_deg[NN];
__device__ int   g_cursor[NN];
__device__ int   g_off[NN + 1];
__device__ int   g_csr[EE];
__device__ int   g_bsum[NB];
__device__ int   g_bpre[NB];
__device__ int   g_is32;   // 1 if edge_index buffer is int32, 0 if int64

// ---------------- init + dtype detection -------------------------------------
__global__ void init_kernel() {
    int i = blockIdx.x * blockDim.x + threadIdx.x;
    if (i < NN) { g_deg[i] = 0; g_cursor[i] = 0; }
    if (i == 0) g_is32 = 0;
}

// Reference declares int64 but JAX default (x64 off) silently yields int32.
// Interpreted as int64, int32 data blows past [0,NN) almost surely.
__global__ void detect_kernel(const void* __restrict__ ei) {
    long long v = ((const long long*)ei)[threadIdx.x];   // 1024 threads
    if (v < 0 || v >= (long long)NN) g_is32 = 1;
}

__device__ __forceinline__ int edge_src(const void* ei, int e) {
    if (g_is32) return ((const int*)ei)[e];
    return (int)((const long long*)ei)[e];
}
__device__ __forceinline__ int edge_dst(const void* ei, int e) {
    if (g_is32) return ((const int*)ei)[EE + e];
    return (int)((const long long*)ei)[EE + e];
}

// ---------------- CSR build ---------------------------------------------------
__global__ void hist_kernel(const void* __restrict__ ei) {
    int e = blockIdx.x * blockDim.x + threadIdx.x;
    if (e < EE) {
        int dst = edge_dst(ei, e);
        if ((unsigned)dst < (unsigned)NN)
            atomicAdd(&g_deg[dst], 1);
    }
}

// 3-phase parallel exclusive scan of g_deg -> g_off
__global__ void scan1_kernel() {
    __shared__ int wsum[32];
    int tid = threadIdx.x, lane = tid & 31, wid = tid >> 5;
    int i = blockIdx.x * 1024 + tid;
    int v = (i < NN) ? g_deg[i] : 0;
    int s = v;
    #pragma unroll
    for (int d = 1; d < 32; d <<= 1) {
        int t = __shfl_up_sync(0xffffffffu, s, d);
        if (lane >= d) s += t;
    }
    if (lane == 31) wsum[wid] = s;
    __syncthreads();
    if (wid == 0) {
        int ws = wsum[lane];
        #pragma unroll
        for (int d = 1; d < 32; d <<= 1) {
            int t = __shfl_up_sync(0xffffffffu, ws, d);
            if (lane >= d) ws += t;
        }
        wsum[lane] = ws;
    }
    __syncthreads();
    int excl = (s - v) + (wid ? wsum[wid - 1] : 0);
    if (i < NN) g_off[i] = excl;
    if (tid == 1023) g_bsum[blockIdx.x] = excl + v;
}

__global__ void scan2_kernel() {   // 1 block, 64 threads (NB=49)
    __shared__ int w0;
    int t = threadIdx.x, lane = t & 31;
    int v = (t < NB) ? g_bsum[t] : 0;
    int s = v;
    #pragma unroll
    for (int d = 1; d < 32; d <<= 1) {
        int x = __shfl_up_sync(0xffffffffu, s, d);
        if (lane >= d) s += x;
    }
    if (t == 31) w0 = s;
    __syncthreads();
    int incl = s + ((t >= 32) ? w0 : 0);
    if (t < NB) g_bpre[t] = incl - v;
    if (t == 63) g_off[NN] = incl;   // total (tail v=0)
}

__global__ void scan3_kernel() {
    int i = blockIdx.x * 1024 + threadIdx.x;
    if (i < NN) g_off[i] += g_bpre[i >> 10];
}

__global__ void fill_kernel(const void* __restrict__ ei) {
    int e = blockIdx.x * blockDim.x + threadIdx.x;
    if (e < EE) {
        int src = edge_src(ei, e);
        int dst = edge_dst(ei, e);
        if ((unsigned)dst < (unsigned)NN && (unsigned)src < (unsigned)NN) {
            int pos = g_off[dst] + atomicAdd(&g_cursor[dst], 1);
            if ((unsigned)pos < (unsigned)EE)
                g_csr[pos] = src;
        }
    }
}

// ---------------- 3xTF32 tensor-core GEMM ------------------------------------
__device__ __forceinline__ uint32_t f2tf32(float f) {
    uint32_t r;
    asm("cvt.rna.tf32.f32 %0, %1;" : "=r"(r) : "f"(f));
    return r;
}
__device__ __forceinline__ void tf32_split(float v, uint32_t& hi, uint32_t& lo) {
    hi = f2tf32(v);
    lo = f2tf32(v - __uint_as_float(hi));
}
__device__ __forceinline__ void mma8(float* c, const uint32_t* a, uint32_t b0, uint32_t b1) {
    asm("mma.sync.aligned.m16n8k8.row.col.f32.tf32.tf32.f32 "
        "{%0,%1,%2,%3},{%4,%5,%6,%7},{%8,%9},{%0,%1,%2,%3};"
        : "+f"(c[0]), "+f"(c[1]), "+f"(c[2]), "+f"(c[3])
        : "r"(a[0]), "r"(a[1]), "r"(a[2]), "r"(a[3]), "r"(b0), "r"(b1));
}

#define KC 32

// y = x @ W + b.  grid.y selects (Wq->g_q, Wk->g_k, Wv->g_v, Wskip->d_out)
__global__ __launch_bounds__(256) void gemm_tf32_kernel(
    const float* __restrict__ x,
    const float* __restrict__ Wq, const float* __restrict__ bq,
    const float* __restrict__ Wk, const float* __restrict__ bk,
    const float* __restrict__ Wv, const float* __restrict__ bv,
    const float* __restrict__ Ws, const float* __restrict__ bs,
    float* __restrict__ dout)
{
    const float* W; const float* bias; float* out;
    switch (blockIdx.y) {
        case 0:  W = Wq; bias = bq; out = g_q;  break;
        case 1:  W = Wk; bias = bk; out = g_k;  break;
        case 2:  W = Wv; bias = bv; out = g_v;  break;
        default: W = Ws; bias = bs; out = dout; break;
    }

    __shared__ float xs[128][36];   // pad 36: A-frag LDS conflict-free (4g+tg)
    __shared__ float ws[KC][136];   // pad 136: B-frag LDS conflict-free (8tg+g)

    const int tid = threadIdx.x;
    const int lane = tid & 31, wid = tid >> 5;
    const int warp_m = wid >> 1;    // 0..3 -> 32 rows each
    const int warp_n = wid & 1;     // 0..1 -> 64 cols each
    const int m_base = blockIdx.x * 128;
    const int g  = lane >> 2;       // group 0..7
    const int tg = lane & 3;        // thread-in-group

    float acc[2][8][4];
    #pragma unroll
    for (int a = 0; a < 2; a++)
        #pragma unroll
        for (int b = 0; b < 8; b++)
            #pragma unroll
            for (int c = 0; c < 4; c++) acc[a][b][c] = 0.f;

    for (int kc = 0; kc < DIM; kc += KC) {
        // x tile: 128 rows x KC cols
        #pragma unroll
        for (int i = 0; i < 4; i++) {
            int id  = tid + i * 256;       // 0..1023 float4 slots
            int row = id >> 3;
            int c4  = (id & 7) * 4;
            float4 v = make_float4(0.f, 0.f, 0.f, 0.f);
            int grow = m_base + row;
            if (grow < NN) v = *(const float4*)(x + (size_t)grow * DIM + kc + c4);
            *(float4*)&xs[row][c4] = v;
        }
        // W tile: KC rows x 128 cols
        #pragma unroll
        for (int i = 0; i < 4; i++) {
            int id   = tid + i * 256;
            int krow = id >> 5;
            int c4   = (id & 31) * 4;
            *(float4*)&ws[krow][c4] = *(const float4*)(W + (size_t)(kc + krow) * DIM + c4);
        }
        __syncthreads();

        #pragma unroll
        for (int kk = 0; kk < KC; kk += 8) {
            uint32_t ahi[2][4], alo[2][4];
            #pragma unroll
            for (int tm = 0; tm < 2; tm++) {
                int r0 = warp_m * 32 + tm * 16 + g;
                tf32_split(xs[r0    ][kk + tg    ], ahi[tm][0], alo[tm][0]);
                tf32_split(xs[r0 + 8][kk + tg    ], ahi[tm][1], alo[tm][1]);
                tf32_split(xs[r0    ][kk + tg + 4], ahi[tm][2], alo[tm][2]);
                tf32_split(xs[r0 + 8][kk + tg + 4], ahi[tm][3], alo[tm][3]);
            }
            #pragma unroll
            for (int tn = 0; tn < 8; tn++) {
                int n0 = warp_n * 64 + tn * 8 + g;
                uint32_t bhi0, blo0, bhi1, blo1;
                tf32_split(ws[kk + tg    ][n0], bhi0, blo0);
                tf32_split(ws[kk + tg + 4][n0], bhi1, blo1);
                #pragma unroll
                for (int tm = 0; tm < 2; tm++) {
                    mma8(acc[tm][tn], ahi[tm], bhi0, bhi1);   // hi*hi
                    mma8(acc[tm][tn], ahi[tm], blo0, blo1);   // hi*lo
                    mma8(acc[tm][tn], alo[tm], bhi0, bhi1);   // lo*hi
                }
            }
        }
        __syncthreads();
    }

    // epilogue: bias + store
    #pragma unroll
    for (int tm = 0; tm < 2; tm++) {
        int r = m_base + warp_m * 32 + tm * 16 + g;
        #pragma unroll
        for (int tn = 0; tn < 8; tn++) {
            int c = warp_n * 64 + tn * 8 + tg * 2;
            float b0 = bias[c], b1 = bias[c + 1];
            if (r < NN) {
                float2 o = make_float2(acc[tm][tn][0] + b0, acc[tm][tn][1] + b1);
                *(float2*)(out + (size_t)r * DIM + c) = o;
            }
            if (r + 8 < NN) {
                float2 o = make_float2(acc[tm][tn][2] + b0, acc[tm][tn][3] + b1);
                *(float2*)(out + (size_t)(r + 8) * DIM + c) = o;
            }
        }
    }
}

// ---------------- fused attention: one warp per dst node ---------------------
__global__ void attn_kernel(float* __restrict__ dout) {
    int warp = (blockIdx.x * blockDim.x + threadIdx.x) >> 5;
    if (warp >= NN) return;
    int lane = threadIdx.x & 31;

    const float4 qv = *(const float4*)(g_q + (size_t)warp * DIM + lane * 4);
    float4 acc = make_float4(0.f, 0.f, 0.f, 0.f);
    float denom = 0.f;

    const int e0 = g_off[warp];
    const int e1 = g_off[warp + 1];
    const float inv_sqrt_c = 0.17677669529663688f;  // 1/sqrt(32)

    for (int j = e0; j < e1; ++j) {
        int s = g_csr[j];
        const float4 kv = *(const float4*)(g_k + (size_t)s * DIM + lane * 4);
        float p = qv.x * kv.x + qv.y * kv.y + qv.z * kv.z + qv.w * kv.w;
        p += __shfl_xor_sync(0xffffffffu, p, 1);
        p += __shfl_xor_sync(0xffffffffu, p, 2);
        p += __shfl_xor_sync(0xffffffffu, p, 4);
        float ex = __expf(p * inv_sqrt_c);
        const float4 vv = *(const float4*)(g_v + (size_t)s * DIM + lane * 4);
        acc.x += ex * vv.x; acc.y += ex * vv.y;
        acc.z += ex * vv.z; acc.w += ex * vv.w;
        denom += ex;
    }

    float inv = (denom > 0.f) ? (1.f / denom) : 0.f;
    float4* op = (float4*)(dout + (size_t)warp * DIM + lane * 4);
    float4 cur = *op;   // skip projection from GEMM
    cur.x += acc.x * inv; cur.y += acc.y * inv;
    cur.z += acc.z * inv; cur.w += acc.w * inv;
    *op = cur;
}

// ---------------- launch ------------------------------------------------------
extern "C" void kernel_launch(void* const* d_in, const int* in_sizes, int n_in,
                              void* d_out, int out_size) {
    const float* x   = (const float*)d_in[0];
    const void*  ei  = d_in[1];
    const float* Wq  = (const float*)d_in[2];
    const float* bq  = (const float*)d_in[3];
    const float* Wk  = (const float*)d_in[4];
    const float* bk  = (const float*)d_in[5];
    const float* Wv  = (const float*)d_in[6];
    const float* bv  = (const float*)d_in[7];
    const float* Ws  = (const float*)d_in[8];
    const float* bs  = (const float*)d_in[9];
    float* dout = (float*)d_out;

    init_kernel<<<(NN + 1023) / 1024, 1024>>>();
    detect_kernel<<<1, 1024>>>(ei);
    hist_kernel<<<(EE + 255) / 256, 256>>>(ei);
    scan1_kernel<<<NB, 1024>>>();
    scan2_kernel<<<1, 64>>>();
    scan3_kernel<<<NB, 1024>>>();
    fill_kernel<<<(EE + 255) / 256, 256>>>(ei);

    dim3 ggrid((NN + 127) / 128, 4);
    gemm_tf32_kernel<<<ggrid, 256>>>(x, Wq, bq, Wk, bk, Wv, bv, Ws, bs, dout);

    attn_kernel<<<(NN * 32 + 255) / 256, 256>>>(dout);
}

// round 5
// speedup vs baseline: 1.2647x; 1.0063x over previous
#include <cuda_runtime.h>
#include <cuda_bf16.h>
#include <cstdint>

#define NN 50000
#define EE 800000
#define DIM 128   // IN == H*C == 128
#define NB 49     // ceil(NN/1024)

// ---------------- scratch -----------------------------------------------------
__device__ float          g_q[(size_t)NN * DIM];
__device__ __nv_bfloat16  g_kb[(size_t)NN * DIM];
__device__ __nv_bfloat16  g_vb[(size_t)NN * DIM];
__device__ int   g_deg[NN];
__device__ int   g_cursor[NN];
__device__ int   g_off[NN + 1];
__device__ int   g_csr[EE];
__device__ int   g_bsum[NB];
__device__ int   g_bpre[NB];
__device__ int   g_is32;   // 1 if edge_index buffer is int32, 0 if int64

// ---------------- init + dtype detection -------------------------------------
__global__ void init_kernel() {
    int i = blockIdx.x * blockDim.x + threadIdx.x;
    if (i < NN) { g_deg[i] = 0; g_cursor[i] = 0; }
    if (i == 0) g_is32 = 0;
}

// Reference declares int64 but JAX default (x64 off) silently yields int32.
// Interpreted as int64, int32 data blows past [0,NN) almost surely.
__global__ void detect_kernel(const void* __restrict__ ei) {
    long long v = ((const long long*)ei)[threadIdx.x];   // 1024 threads
    if (v < 0 || v >= (long long)NN) g_is32 = 1;
}

__device__ __forceinline__ int edge_src(const void* ei, int e) {
    if (g_is32) return ((const int*)ei)[e];
    return (int)((const long long*)ei)[e];
}
__device__ __forceinline__ int edge_dst(const void* ei, int e) {
    if (g_is32) return ((const int*)ei)[EE + e];
    return (int)((const long long*)ei)[EE + e];
}

// ---------------- CSR build ---------------------------------------------------
__global__ void hist_kernel(const void* __restrict__ ei) {
    int e = blockIdx.x * blockDim.x + threadIdx.x;
    if (e < EE) {
        int dst = edge_dst(ei, e);
        if ((unsigned)dst < (unsigned)NN)
            atomicAdd(&g_deg[dst], 1);
    }
}

// 3-phase parallel exclusive scan of g_deg -> g_off
__global__ void scan1_kernel() {
    __shared__ int wsum[32];
    int tid = threadIdx.x, lane = tid & 31, wid = tid >> 5;
    int i = blockIdx.x * 1024 + tid;
    int v = (i < NN) ? g_deg[i] : 0;
    int s = v;
    #pragma unroll
    for (int d = 1; d < 32; d <<= 1) {
        int t = __shfl_up_sync(0xffffffffu, s, d);
        if (lane >= d) s += t;
    }
    if (lane == 31) wsum[wid] = s;
    __syncthreads();
    if (wid == 0) {
        int ws = wsum[lane];
        #pragma unroll
        for (int d = 1; d < 32; d <<= 1) {
            int t = __shfl_up_sync(0xffffffffu, ws, d);
            if (lane >= d) ws += t;
        }
        wsum[lane] = ws;
    }
    __syncthreads();
    int excl = (s - v) + (wid ? wsum[wid - 1] : 0);
    if (i < NN) g_off[i] = excl;
    if (tid == 1023) g_bsum[blockIdx.x] = excl + v;
}

__global__ void scan2_kernel() {   // 1 block, 64 threads (NB=49)
    __shared__ int w0;
    int t = threadIdx.x, lane = t & 31;
    int v = (t < NB) ? g_bsum[t] : 0;
    int s = v;
    #pragma unroll
    for (int d = 1; d < 32; d <<= 1) {
        int x = __shfl_up_sync(0xffffffffu, s, d);
        if (lane >= d) s += x;
    }
    if (t == 31) w0 = s;
    __syncthreads();
    int incl = s + ((t >= 32) ? w0 : 0);
    if (t < NB) g_bpre[t] = incl - v;
    if (t == 63) g_off[NN] = incl;   // total (tail v=0)
}

__global__ void scan3_kernel() {
    int i = blockIdx.x * 1024 + threadIdx.x;
    if (i < NN) g_off[i] += g_bpre[i >> 10];
}

__global__ void fill_kernel(const void* __restrict__ ei) {
    int e = blockIdx.x * blockDim.x + threadIdx.x;
    if (e < EE) {
        int src = edge_src(ei, e);
        int dst = edge_dst(ei, e);
        if ((unsigned)dst < (unsigned)NN && (unsigned)src < (unsigned)NN) {
            int pos = g_off[dst] + atomicAdd(&g_cursor[dst], 1);
            if ((unsigned)pos < (unsigned)EE)
                g_csr[pos] = src;
        }
    }
}

// ---------------- 3xTF32 tensor-core GEMM ------------------------------------
__device__ __forceinline__ uint32_t f2tf32(float f) {
    uint32_t r;
    asm("cvt.rna.tf32.f32 %0, %1;" : "=r"(r) : "f"(f));
    return r;
}
__device__ __forceinline__ void tf32_split(float v, uint32_t& hi, uint32_t& lo) {
    hi = f2tf32(v);
    lo = f2tf32(v - __uint_as_float(hi));
}
__device__ __forceinline__ void mma8(float* c, const uint32_t* a, uint32_t b0, uint32_t b1) {
    asm("mma.sync.aligned.m16n8k8.row.col.f32.tf32.tf32.f32 "
        "{%0,%1,%2,%3},{%4,%5,%6,%7},{%8,%9},{%0,%1,%2,%3};"
        : "+f"(c[0]), "+f"(c[1]), "+f"(c[2]), "+f"(c[3])
        : "r"(a[0]), "r"(a[1]), "r"(a[2]), "r"(a[3]), "r"(b0), "r"(b1));
}

#define KC 32

// y = x @ W + b.  grid.y: 0->g_q(f32) 1->g_kb(bf16) 2->g_vb(bf16) 3->dout(f32)
__global__ __launch_bounds__(256) void gemm_tf32_kernel(
    const float* __restrict__ x,
    const float* __restrict__ Wq, const float* __restrict__ bq,
    const float* __restrict__ Wk, const float* __restrict__ bk,
    const float* __restrict__ Wv, const float* __restrict__ bv,
    const float* __restrict__ Ws, const float* __restrict__ bs,
    float* __restrict__ dout)
{
    const float* W; const float* bias;
    float* outf = nullptr; __nv_bfloat16* outb = nullptr;
    switch (blockIdx.y) {
        case 0:  W = Wq; bias = bq; outf = g_q;  break;
        case 1:  W = Wk; bias = bk; outb = g_kb; break;
        case 2:  W = Wv; bias = bv; outb = g_vb; break;
        default: W = Ws; bias = bs; outf = dout; break;
    }

    __shared__ float xs[128][36];   // pad 36: A-frag LDS conflict-free
    __shared__ float ws[KC][136];   // pad 136: B-frag LDS conflict-free

    const int tid = threadIdx.x;
    const int lane = tid & 31, wid = tid >> 5;
    const int warp_m = wid >> 1;    // 0..3 -> 32 rows each
    const int warp_n = wid & 1;     // 0..1 -> 64 cols each
    const int m_base = blockIdx.x * 128;
    const int g  = lane >> 2;       // group 0..7
    const int tg = lane & 3;        // thread-in-group

    float acc[2][8][4];
    #pragma unroll
    for (int a = 0; a < 2; a++)
        #pragma unroll
        for (int b = 0; b < 8; b++)
            #pragma unroll
            for (int c = 0; c < 4; c++) acc[a][b][c] = 0.f;

    for (int kc = 0; kc < DIM; kc += KC) {
        #pragma unroll
        for (int i = 0; i < 4; i++) {
            int id  = tid + i * 256;
            int row = id >> 3;
            int c4  = (id & 7) * 4;
            float4 v = make_float4(0.f, 0.f, 0.f, 0.f);
            int grow = m_base + row;
            if (grow < NN) v = *(const float4*)(x + (size_t)grow * DIM + kc + c4);
            *(float4*)&xs[row][c4] = v;
        }
        #pragma unroll
        for (int i = 0; i < 4; i++) {
            int id   = tid + i * 256;
            int krow = id >> 5;
            int c4   = (id & 31) * 4;
            *(float4*)&ws[krow][c4] = *(const float4*)(W + (size_t)(kc + krow) * DIM + c4);
        }
        __syncthreads();

        #pragma unroll
        for (int kk = 0; kk < KC; kk += 8) {
            uint32_t ahi[2][4], alo[2][4];
            #pragma unroll
            for (int tm = 0; tm < 2; tm++) {
                int r0 = warp_m * 32 + tm * 16 + g;
                tf32_split(xs[r0    ][kk + tg    ], ahi[tm][0], alo[tm][0]);
                tf32_split(xs[r0 + 8][kk + tg    ], ahi[tm][1], alo[tm][1]);
                tf32_split(xs[r0    ][kk + tg + 4], ahi[tm][2], alo[tm][2]);
                tf32_split(xs[r0 + 8][kk + tg + 4], ahi[tm][3], alo[tm][3]);
            }
            #pragma unroll
            for (int tn = 0; tn < 8; tn++) {
                int n0 = warp_n * 64 + tn * 8 + g;
                uint32_t bhi0, blo0, bhi1, blo1;
                tf32_split(ws[kk + tg    ][n0], bhi0, blo0);
                tf32_split(ws[kk + tg + 4][n0], bhi1, blo1);
                #pragma unroll
                for (int tm = 0; tm < 2; tm++) {
                    mma8(acc[tm][tn], ahi[tm], bhi0, bhi1);   // hi*hi
                    mma8(acc[tm][tn], ahi[tm], blo0, blo1);   // hi*lo
                    mma8(acc[tm][tn], alo[tm], bhi0, bhi1);   // lo*hi
                }
            }
        }
        __syncthreads();
    }

    // epilogue: bias + store (fp32 or bf16 depending on output)
    #pragma unroll
    for (int tm = 0; tm < 2; tm++) {
        int r = m_base + warp_m * 32 + tm * 16 + g;
        #pragma unroll
        for (int tn = 0; tn < 8; tn++) {
            int c = warp_n * 64 + tn * 8 + tg * 2;
            float b0 = bias[c], b1 = bias[c + 1];
            float v00 = acc[tm][tn][0] + b0, v01 = acc[tm][tn][1] + b1;
            float v10 = acc[tm][tn][2] + b0, v11 = acc[tm][tn][3] + b1;
            if (outf) {
                if (r < NN)
                    *(float2*)(outf + (size_t)r * DIM + c) = make_float2(v00, v01);
                if (r + 8 < NN)
                    *(float2*)(outf + (size_t)(r + 8) * DIM + c) = make_float2(v10, v11);
            } else {
                if (r < NN)
                    *(__nv_bfloat162*)(outb + (size_t)r * DIM + c) =
                        __floats2bfloat162_rn(v00, v01);
                if (r + 8 < NN)
                    *(__nv_bfloat162*)(outb + (size_t)(r + 8) * DIM + c) =
                        __floats2bfloat162_rn(v10, v11);
            }
        }
    }
}

// ---------------- fused attention: one warp per dst node ---------------------
// k,v gathered as bf16 (halves L2 traffic); q and accumulation in fp32.
__global__ void attn_kernel(float* __restrict__ dout) {
    int warp = (blockIdx.x * blockDim.x + threadIdx.x) >> 5;
    if (warp >= NN) return;
    int lane = threadIdx.x & 31;

    const float4 qv = *(const float4*)(g_q + (size_t)warp * DIM + lane * 4);
    float4 acc = make_float4(0.f, 0.f, 0.f, 0.f);
    float denom = 0.f;

    const int e0 = g_off[warp];
    const int e1 = g_off[warp + 1];
    const float inv_sqrt_c = 0.17677669529663688f;  // 1/sqrt(32)

    for (int j = e0; j < e1; ++j) {
        int s = g_csr[j];
        uint2 kr = *(const uint2*)(g_kb + (size_t)s * DIM + lane * 4);
        float2 k01 = __bfloat1622float2(*(__nv_bfloat162*)&kr.x);
        float2 k23 = __bfloat1622float2(*(__nv_bfloat162*)&kr.y);
        float p = qv.x * k01.x + qv.y * k01.y + qv.z * k23.x + qv.w * k23.y;
        p += __shfl_xor_sync(0xffffffffu, p, 1);
        p += __shfl_xor_sync(0xffffffffu, p, 2);
        p += __shfl_xor_sync(0xffffffffu, p, 4);
        float ex = __expf(p * inv_sqrt_c);
        uint2 vr = *(const uint2*)(g_vb + (size_t)s * DIM + lane * 4);
        float2 v01 = __bfloat1622float2(*(__nv_bfloat162*)&vr.x);
        float2 v23 = __bfloat1622float2(*(__nv_bfloat162*)&vr.y);
        acc.x += ex * v01.x; acc.y += ex * v01.y;
        acc.z += ex * v23.x; acc.w += ex * v23.y;
        denom += ex;
    }

    float inv = (denom > 0.f) ? (1.f / denom) : 0.f;
    float4* op = (float4*)(dout + (size_t)warp * DIM + lane * 4);
    float4 cur = *op;   // skip projection from GEMM
    cur.x += acc.x * inv; cur.y += acc.y * inv;
    cur.z += acc.z * inv; cur.w += acc.w * inv;
    *op = cur;
}

// ---------------- launch: fork-join so CSR build overlaps the GEMM ------------
extern "C" void kernel_launch(void* const* d_in, const int* in_sizes, int n_in,
                              void* d_out, int out_size) {
    const float* x   = (const float*)d_in[0];
    const void*  ei  = d_in[1];
    const float* Wq  = (const float*)d_in[2];
    const float* bq  = (const float*)d_in[3];
    const float* Wk  = (const float*)d_in[4];
    const float* bk  = (const float*)d_in[5];
    const float* Wv  = (const float*)d_in[6];
    const float* bv  = (const float*)d_in[7];
    const float* Ws  = (const float*)d_in[8];
    const float* bs  = (const float*)d_in[9];
    float* dout = (float*)d_out;

    // fresh per call (called only a handful of times; never destroyed to avoid
    // destroying a capture-participating stream mid-capture)
    cudaStream_t s2;
    cudaStreamCreateWithFlags(&s2, cudaStreamNonBlocking);
    cudaEvent_t ev_fork, ev_join;
    cudaEventCreateWithFlags(&ev_fork, cudaEventDisableTiming);
    cudaEventCreateWithFlags(&ev_join, cudaEventDisableTiming);

    cudaEventRecord(ev_fork, 0);
    cudaStreamWaitEvent(s2, ev_fork, 0);

    // side stream: CSR build chain
    init_kernel<<<(NN + 1023) / 1024, 1024, 0, s2>>>();
    detect_kernel<<<1, 1024, 0, s2>>>(ei);
    hist_kernel<<<(EE + 255) / 256, 256, 0, s2>>>(ei);
    scan1_kernel<<<NB, 1024, 0, s2>>>();
    scan2_kernel<<<1, 64, 0, s2>>>();
    scan3_kernel<<<NB, 1024, 0, s2>>>();
    fill_kernel<<<(EE + 255) / 256, 256, 0, s2>>>(ei);
    cudaEventRecord(ev_join, s2);

    // main stream: GEMM runs concurrently with CSR build
    dim3 ggrid((NN + 127) / 128, 4);
    gemm_tf32_kernel<<<ggrid, 256>>>(x, Wq, bq, Wk, bk, Wv, bv, Ws, bs, dout);

    cudaStreamWaitEvent(0, ev_join, 0);
    attn_kernel<<<(NN * 32 + 255) / 256, 256>>>(dout);
}